// round 6
// baseline (speedup 1.0000x reference)
#include <cuda_runtime.h>
#include <cstdint>

// MoEAllReduce: fused expert-weighted reduction + residual add + RMSNorm.
// out[0 : T*H]     = hidden_states
// out[T*H : 2*T*H] = output_residual
//
// Fast path (E=8, H=4096, 512 thr): one CTA per token row, each thread owns
// one 256-bit (v8) chunk -> whole row covered in a single vector op per
// stream. sm_10x 256-bit LDG/STG via inline PTX, streaming (.cs) hints.
// Batched load phase -> block reduce -> batched store phase.

#define NTHREADS 512
#define MAX_ITEMS 8   // generic fallback supports H up to 4*512*8 = 16384

__device__ __forceinline__ float warp_reduce_sum(float v) {
#pragma unroll
    for (int off = 16; off > 0; off >>= 1)
        v += __shfl_xor_sync(0xFFFFFFFFu, v, off);
    return v;
}

// ---------------- 256-bit vector helpers (sm_100+) ----------------
struct F8 { float v[8]; };

__device__ __forceinline__ void ldg_cs_v8(F8& d, const float* p) {
    asm volatile("ld.global.cs.v8.f32 {%0,%1,%2,%3,%4,%5,%6,%7}, [%8];"
        : "=f"(d.v[0]), "=f"(d.v[1]), "=f"(d.v[2]), "=f"(d.v[3]),
          "=f"(d.v[4]), "=f"(d.v[5]), "=f"(d.v[6]), "=f"(d.v[7])
        : "l"(p));
}

__device__ __forceinline__ void ldg_nc_v8(F8& d, const float* p) {
    asm volatile("ld.global.nc.v8.f32 {%0,%1,%2,%3,%4,%5,%6,%7}, [%8];"
        : "=f"(d.v[0]), "=f"(d.v[1]), "=f"(d.v[2]), "=f"(d.v[3]),
          "=f"(d.v[4]), "=f"(d.v[5]), "=f"(d.v[6]), "=f"(d.v[7])
        : "l"(p));
}

__device__ __forceinline__ void stg_cs_v8(float* p, const F8& d) {
    asm volatile("st.global.cs.v8.f32 [%0], {%1,%2,%3,%4,%5,%6,%7,%8};"
        :: "l"(p),
           "f"(d.v[0]), "f"(d.v[1]), "f"(d.v[2]), "f"(d.v[3]),
           "f"(d.v[4]), "f"(d.v[5]), "f"(d.v[6]), "f"(d.v[7])
        : "memory");
}

// ---------------- fast path: E=8, H = 8*NTHREADS ----------------
__global__ __launch_bounds__(NTHREADS, 3)
void moe_v8_kernel(
    const float* __restrict__ residual,     // [T, H]
    const float* __restrict__ norm_weight,  // [H]
    const float* __restrict__ scale,        // [E, T]
    const float* __restrict__ A,            // [E, T, H]
    const float* __restrict__ token,        // [T, H]
    float* __restrict__ hidden,             // [T, H]
    float* __restrict__ out_res,            // [T, H]
    int T, int H)
{
    const int t = blockIdx.x;
    const int tid = threadIdx.x;

    __shared__ float s_scale[8];
    __shared__ float s_warp[NTHREADS / 32];
    __shared__ float s_inv;

    if (tid < 8) s_scale[tid] = scale[(size_t)tid * T + t];
    __syncthreads();

    const size_t rowOff = (size_t)t * H + (size_t)tid * 8;   // 32B-aligned
    const size_t expStride = (size_t)T * H;

    F8 acc;
    {
        F8 r, k;
        ldg_cs_v8(r, residual + rowOff);
        ldg_cs_v8(k, token + rowOff);
#pragma unroll
        for (int j = 0; j < 8; j++) acc.v[j] = r.v[j] + k.v[j];
    }

#pragma unroll
    for (int e = 0; e < 8; e++) {
        const float se = s_scale[e];
        F8 v;
        ldg_cs_v8(v, A + (size_t)e * expStride + rowOff);
#pragma unroll
        for (int j = 0; j < 8; j++) acc.v[j] = fmaf(se, v.v[j], acc.v[j]);
    }

    float ss = 0.0f;
#pragma unroll
    for (int j = 0; j < 8; j++) ss += acc.v[j] * acc.v[j];

    // Block reduction of sum-of-squares
    ss = warp_reduce_sum(ss);
    const int wid = tid >> 5;
    const int lid = tid & 31;
    if (lid == 0) s_warp[wid] = ss;
    __syncthreads();
    if (wid == 0) {
        float v = (lid < NTHREADS / 32) ? s_warp[lid] : 0.0f;
        v = warp_reduce_sum(v);
        if (lid == 0) s_inv = rsqrtf(v / (float)H + 1e-5f);
    }
    __syncthreads();
    const float inv = s_inv;

    F8 w;
    ldg_nc_v8(w, norm_weight + (size_t)tid * 8);   // L2-resident broadcast

    F8 hOut;
#pragma unroll
    for (int j = 0; j < 8; j++) hOut.v[j] = acc.v[j] * inv * w.v[j];

    stg_cs_v8(out_res + rowOff, acc);
    stg_cs_v8(hidden + rowOff, hOut);
}

// ---------------- generic fallback (float4, R5 structure) ----------------
__global__ __launch_bounds__(NTHREADS, 3)
void moe_generic_kernel(
    const float* __restrict__ residual,
    const float* __restrict__ norm_weight,
    const float* __restrict__ scale,
    const float* __restrict__ A,
    const float* __restrict__ token,
    float* __restrict__ hidden,
    float* __restrict__ out_res,
    int E, int T, int H)
{
    const int t = blockIdx.x;
    const int tid = threadIdx.x;
    const int h4 = H >> 2;
    const int items = h4 / NTHREADS;

    __shared__ float s_scale[32];
    __shared__ float s_warp[NTHREADS / 32];
    __shared__ float s_inv;

    if (tid < E) s_scale[tid] = scale[(size_t)tid * T + t];
    __syncthreads();

    const float4* __restrict__ res4 = (const float4*)(residual + (size_t)t * H);
    const float4* __restrict__ tok4 = (const float4*)(token    + (size_t)t * H);
    const float4* __restrict__ A4   = (const float4*)A;
    const size_t rowStride4 = (size_t)T * h4;
    const size_t rowBase4   = (size_t)t * h4;

    float4 acc[MAX_ITEMS];
    float ss = 0.0f;

#pragma unroll
    for (int i = 0; i < MAX_ITEMS; i++) {
        if (i >= items) break;
        const int idx = tid + i * NTHREADS;
        float4 r = __ldcs(&res4[idx]);
        float4 k = __ldcs(&tok4[idx]);
        float4 a;
        a.x = r.x + k.x; a.y = r.y + k.y; a.z = r.z + k.z; a.w = r.w + k.w;
        for (int e = 0; e < E; e++) {
            const float se = s_scale[e];
            float4 v = __ldcs(&A4[(size_t)e * rowStride4 + rowBase4 + idx]);
            a.x = fmaf(se, v.x, a.x);
            a.y = fmaf(se, v.y, a.y);
            a.z = fmaf(se, v.z, a.z);
            a.w = fmaf(se, v.w, a.w);
        }
        acc[i] = a;
        ss += a.x * a.x + a.y * a.y + a.z * a.z + a.w * a.w;
    }

    ss = warp_reduce_sum(ss);
    const int wid = tid >> 5;
    const int lid = tid & 31;
    if (lid == 0) s_warp[wid] = ss;
    __syncthreads();
    if (wid == 0) {
        float v = (lid < NTHREADS / 32) ? s_warp[lid] : 0.0f;
        v = warp_reduce_sum(v);
        if (lid == 0) s_inv = rsqrtf(v / (float)H + 1e-5f);
    }
    __syncthreads();
    const float inv = s_inv;

    const float4* __restrict__ w4 = (const float4*)norm_weight;
    float4* __restrict__ o_res4 = (float4*)(out_res + (size_t)t * H);
    float4* __restrict__ o_hid4 = (float4*)(hidden  + (size_t)t * H);

#pragma unroll
    for (int i = 0; i < MAX_ITEMS; i++) {
        if (i >= items) break;
        const int idx = tid + i * NTHREADS;
        float4 a = acc[i];
        float4 w = __ldg(&w4[idx]);
        float4 hOut;
        hOut.x = a.x * inv * w.x;
        hOut.y = a.y * inv * w.y;
        hOut.z = a.z * inv * w.z;
        hOut.w = a.w * inv * w.w;
        __stcs(&o_res4[idx], a);
        __stcs(&o_hid4[idx], hOut);
    }
}

extern "C" void kernel_launch(void* const* d_in, const int* in_sizes, int n_in,
                              void* d_out, int out_size)
{
    const float* residual = (const float*)d_in[0];   // [T, H]
    const float* weight   = (const float*)d_in[1];   // [H]
    const float* scale    = (const float*)d_in[2];   // [E, T]
    const float* A        = (const float*)d_in[3];   // [E, T, H]
    const float* token    = (const float*)d_in[4];   // [T, H]

    const int H = in_sizes[1];
    const int TH = in_sizes[0];
    const int T = TH / H;
    const int E = in_sizes[2] / T;

    float* hidden  = (float*)d_out;              // [T, H]
    float* out_res = (float*)d_out + (size_t)TH; // [T, H]

    dim3 grid(T);
    dim3 block(NTHREADS);
    if (E == 8 && H == 8 * NTHREADS) {
        moe_v8_kernel<<<grid, block>>>(
            residual, weight, scale, A, token, hidden, out_res, T, H);
    } else {
        moe_generic_kernel<<<grid, block>>>(
            residual, weight, scale, A, token, hidden, out_res, E, T, H);
    }
}